// round 16
// baseline (speedup 1.0000x reference)
#include <cuda_runtime.h>
#include <cuda_bf16.h>
#include <math.h>
#include <stdint.h>

// Problem constants
#define BB   16
#define SS   512
#define HH   768
#define LL   12
#define NHH  12
#define DHH  64
#define FFD  3072
#define KK   9
#define TOK  (BB*SS)          // 8192
#define H3   (3*HH)           // 2304

// ---------------- scratch (static device globals; no allocation) ----------------
__device__ __align__(16) float g_x[TOK*HH];
__device__ __align__(16) float g_tmp[TOK*HH];
__device__ __align__(16) float g_tmp2[TOK*HH];
__device__ __align__(16) float g_emis[TOK*KK];
__device__ float g_loss[1];

// bf16 hi/lo split arrays (operands for tensor-core GEMMs)
__device__ __align__(16) __nv_bfloat16 g_xh[TOK*HH],    g_xl[TOK*HH];
__device__ __align__(16) __nv_bfloat16 g_qkvh[TOK*H3],  g_qkvl[TOK*H3];
__device__ __align__(16) __nv_bfloat16 g_ffh[TOK*FFD],  g_ffl[TOK*FFD];
__device__ __align__(16) __nv_bfloat16 g_ctxh[TOK*HH],  g_ctxl[TOK*HH];
__device__ __align__(16) __nv_bfloat16 g_wqkvh[LL*HH*H3],  g_wqkvl[LL*HH*H3];
__device__ __align__(16) __nv_bfloat16 g_woh[LL*HH*HH],    g_wol[LL*HH*HH];
__device__ __align__(16) __nv_bfloat16 g_w1h[LL*HH*FFD],   g_w1l[LL*HH*FFD];
__device__ __align__(16) __nv_bfloat16 g_w2h[LL*FFD*HH],   g_w2l[LL*FFD*HH];

// ---------------- helpers ----------------
__device__ __forceinline__ float warp_sum(float v) {
    #pragma unroll
    for (int o = 16; o; o >>= 1) v += __shfl_xor_sync(0xffffffffu, v, o);
    return v;
}
__device__ __forceinline__ float warp_max(float v) {
    #pragma unroll
    for (int o = 16; o; o >>= 1) v = fmaxf(v, __shfl_xor_sync(0xffffffffu, v, o));
    return v;
}
__device__ float block_sum_256(float v) {
    __shared__ float red[8];
    __shared__ float total;
    int lane = threadIdx.x & 31, w = threadIdx.x >> 5;
    v = warp_sum(v);
    if (lane == 0) red[w] = v;
    __syncthreads();
    if (w == 0) {
        float x = (lane < 8) ? red[lane] : 0.f;
        x = warp_sum(x);
        if (lane == 0) total = x;
    }
    __syncthreads();
    float r = total;
    __syncthreads();
    return r;
}
__device__ __forceinline__ float gelu_f(float x) {
    return 0.5f * x * (1.f + erff(x * 0.7071067811865475f));
}
__device__ __forceinline__ void split1(float v, __nv_bfloat16& h, __nv_bfloat16& l) {
    h = __float2bfloat16(v);
    l = __float2bfloat16(v - __bfloat162float(h));
}

// ---------------- PTX primitives ----------------
__device__ __forceinline__ uint32_t smem_u32(const void* p) {
    uint32_t a;
    asm("{ .reg .u64 t; cvta.to.shared.u64 t, %1; cvt.u32.u64 %0, t; }" : "=r"(a) : "l"(p));
    return a;
}
__device__ __forceinline__ void mma16816(float* d, const uint32_t* a, const uint32_t* b) {
    asm volatile(
        "mma.sync.aligned.m16n8k16.row.col.f32.bf16.bf16.f32 "
        "{%0,%1,%2,%3},{%4,%5,%6,%7},{%8,%9},{%0,%1,%2,%3};"
        : "+f"(d[0]), "+f"(d[1]), "+f"(d[2]), "+f"(d[3])
        : "r"(a[0]), "r"(a[1]), "r"(a[2]), "r"(a[3]), "r"(b[0]), "r"(b[1]));
}
__device__ __forceinline__ void ldm4(uint32_t* r, uint32_t s) {
    asm volatile("ldmatrix.sync.aligned.m8n8.x4.shared.b16 {%0,%1,%2,%3}, [%4];"
        : "=r"(r[0]), "=r"(r[1]), "=r"(r[2]), "=r"(r[3]) : "r"(s));
}
__device__ __forceinline__ void ldm4t(uint32_t* r, uint32_t s) {
    asm volatile("ldmatrix.sync.aligned.m8n8.x4.trans.shared.b16 {%0,%1,%2,%3}, [%4];"
        : "=r"(r[0]), "=r"(r[1]), "=r"(r[2]), "=r"(r[3]) : "r"(s));
}
__device__ __forceinline__ void cpa16(uint32_t s, const void* g) {
    asm volatile("cp.async.cg.shared.global [%0], [%1], 16;" :: "r"(s), "l"(g));
}
#define CPA_COMMIT() asm volatile("cp.async.commit_group;" ::: "memory")
__device__ __forceinline__ void cpa_wait1() { asm volatile("cp.async.wait_group 1;" ::: "memory"); }
__device__ __forceinline__ void cpa_wait0() { asm volatile("cp.async.wait_group 0;" ::: "memory"); }
__device__ __forceinline__ uint32_t packbf2(__nv_bfloat16 a, __nv_bfloat16 b) {
    __nv_bfloat162 t; t.x = a; t.y = b;
    return *(uint32_t*)&t;
}

// =================================================================================
// bf16x3 tensor-core GEMM, 128x128 tile (Wo / FF2 with split-K).
// EPI: bit0 GELU, bit1 split-bf16 output, bit2 residual, bit3 split-K (grid.z=2).
// =================================================================================
template<int EPI>
__global__ __launch_bounds__(256, 2) void g2(
    int Kd,
    const __nv_bfloat16* __restrict__ Ah, const __nv_bfloat16* __restrict__ Al, int lda,
    const __nv_bfloat16* __restrict__ Bh, const __nv_bfloat16* __restrict__ Bl, int ldb,
    float* __restrict__ Cf, __nv_bfloat16* __restrict__ Ch, __nv_bfloat16* __restrict__ Cl,
    int ldc, const float* __restrict__ bias, const float* __restrict__ res,
    float* __restrict__ Cf2)
{
    constexpr int STAGE = 32768;   // Ah 8K | Al 8K | Bh 8K | Bl 8K
    extern __shared__ char dsm[];

    if (EPI & 8) {
        int z = blockIdx.z;
        Ah += (size_t)z * Kd;          Al += (size_t)z * Kd;
        Bh += (size_t)z * Kd * ldb;    Bl += (size_t)z * Kd * ldb;
    }

    const int tid = threadIdx.x, wid = tid >> 5, lane = tid & 31;
    const int row0 = blockIdx.y * 128, col0 = blockIdx.x * 128;
    const int warpM = (wid >> 1) * 32, warpN = (wid & 1) * 64;

    uint32_t sbase = (smem_u32(dsm) + 1023) & ~1023u;

    float acc[2][8][4];
    #pragma unroll
    for (int a = 0; a < 2; a++)
        #pragma unroll
        for (int b = 0; b < 8; b++)
            #pragma unroll
            for (int c = 0; c < 4; c++) acc[a][b][c] = 0.f;

    auto LOADST = [&](int st, int kt) {
        uint32_t sa = sbase + st * STAGE;
        #pragma unroll
        for (int i = 0; i < 2; i++) {
            int cid = tid + 256 * i;
            int r = cid >> 2, c = cid & 3;
            size_t go = (size_t)(row0 + r) * lda + kt * 32 + c * 8;
            uint32_t so = (uint32_t)(r * 64 + ((c ^ ((r >> 1) & 3)) << 4));
            cpa16(sa + so, Ah + go);
            cpa16(sa + 8192 + so, Al + go);
        }
        #pragma unroll
        for (int i = 0; i < 2; i++) {
            int cid = tid + 256 * i;
            int r = cid >> 4, c = cid & 15;
            size_t go = (size_t)(kt * 32 + r) * ldb + col0 + c * 8;
            uint32_t cs = (uint32_t)((c & 8) | ((c & 7) ^ (r & 7)));
            uint32_t so = (uint32_t)(r * 256 + (cs << 4));
            cpa16(sa + 16384 + so, Bh + go);
            cpa16(sa + 24576 + so, Bl + go);
        }
    };

    auto COMP = [&](int st) {
        uint32_t sa = sbase + st * STAGE;
        uint32_t sAl_ = sa + 8192, sBh_ = sa + 16384, sBl_ = sBh_ + 8192;
        #pragma unroll
        for (int ks = 0; ks < 2; ks++) {
            uint32_t ahf[2][4], alf[2][4];
            #pragma unroll
            for (int mf = 0; mf < 2; mf++) {
                int r = warpM + mf * 16 + (lane & 15);
                int ch = ks * 2 + (lane >> 4);
                uint32_t so = (uint32_t)(r * 64 + ((ch ^ ((r >> 1) & 3)) << 4));
                ldm4(ahf[mf], sa + so);
                ldm4(alf[mf], sAl_ + so);
            }
            uint32_t bhf[4][4], blf[4][4];
            #pragma unroll
            for (int g = 0; g < 4; g++) {
                int idx = lane & 7, sel = lane >> 3;
                int k = ks * 16 + (sel & 1) * 8 + idx;
                int c = ((warpN + g * 16) >> 3) + (sel >> 1);
                uint32_t cs = (uint32_t)((c & 8) | ((c & 7) ^ (k & 7)));
                uint32_t so = (uint32_t)(k * 256 + (cs << 4));
                ldm4t(bhf[g], sBh_ + so);
                ldm4t(blf[g], sBl_ + so);
            }
            #pragma unroll
            for (int mf = 0; mf < 2; mf++)
                #pragma unroll
                for (int nf = 0; nf < 8; nf++) {
                    int g = nf >> 1;
                    uint32_t bh[2] = { bhf[g][(nf & 1) * 2], bhf[g][(nf & 1) * 2 + 1] };
                    uint32_t bl[2] = { blf[g][(nf & 1) * 2], blf[g][(nf & 1) * 2 + 1] };
                    mma16816(acc[mf][nf], ahf[mf], bh);
                    mma16816(acc[mf][nf], alf[mf], bh);
                    mma16816(acc[mf][nf], ahf[mf], bl);
                }
        }
    };

    const int nt = Kd / 32;
    LOADST(0, 0); CPA_COMMIT();
    if (nt > 1) { LOADST(1, 1); CPA_COMMIT(); }
    for (int kt = 0; kt < nt; kt++) {
        if (kt + 1 < nt) cpa_wait1(); else cpa_wait0();
        __syncthreads();
        if (kt + 2 < nt) { LOADST((kt + 2) % 3, kt + 2); CPA_COMMIT(); }
        COMP(kt % 3);
    }

    const bool raw = (EPI & 8) && (blockIdx.z == 1);
    #pragma unroll
    for (int mf = 0; mf < 2; mf++)
        #pragma unroll
        for (int nf = 0; nf < 8; nf++) {
            int r = row0 + warpM + mf * 16 + (lane >> 2);
            int c = col0 + warpN + nf * 8 + (lane & 3) * 2;
            if (raw) {
                *(float2*)&Cf2[(size_t)r * ldc + c]       = make_float2(acc[mf][nf][0], acc[mf][nf][1]);
                *(float2*)&Cf2[(size_t)(r + 8) * ldc + c] = make_float2(acc[mf][nf][2], acc[mf][nf][3]);
                continue;
            }
            float b0 = 0.f, b1 = 0.f;
            if (bias) { b0 = bias[c]; b1 = bias[c + 1]; }
            float v0 = acc[mf][nf][0] + b0, v1 = acc[mf][nf][1] + b1;
            float v2 = acc[mf][nf][2] + b0, v3 = acc[mf][nf][3] + b1;
            if (EPI & 4) {
                float2 r0 = *(const float2*)&res[(size_t)r * ldc + c];
                float2 r1 = *(const float2*)&res[(size_t)(r + 8) * ldc + c];
                v0 += r0.x; v1 += r0.y; v2 += r1.x; v3 += r1.y;
            }
            if (EPI & 1) { v0 = gelu_f(v0); v1 = gelu_f(v1); v2 = gelu_f(v2); v3 = gelu_f(v3); }
            if (EPI & 2) {
                __nv_bfloat16 h0, h1, h2, h3, l0, l1, l2, l3;
                split1(v0, h0, l0); split1(v1, h1, l1);
                split1(v2, h2, l2); split1(v3, h3, l3);
                *(uint32_t*)&Ch[(size_t)r * ldc + c]       = packbf2(h0, h1);
                *(uint32_t*)&Cl[(size_t)r * ldc + c]       = packbf2(l0, l1);
                *(uint32_t*)&Ch[(size_t)(r + 8) * ldc + c] = packbf2(h2, h3);
                *(uint32_t*)&Cl[(size_t)(r + 8) * ldc + c] = packbf2(l2, l3);
            } else {
                *(float2*)&Cf[(size_t)r * ldc + c]       = make_float2(v0, v1);
                *(float2*)&Cf[(size_t)(r + 8) * ldc + c] = make_float2(v2, v3);
            }
        }
}

// =================================================================================
// bf16x3 tensor-core GEMM, 256x128 tile (QKV / FF1): halved per-output smem traffic.
// 8 warps, each 64M x 64N. 1 CTA/SM (regs), 3-stage 48KB/stage pipeline.
// EPI: bit0 GELU, bit1 split-bf16 output.
// =================================================================================
template<int EPI>
__global__ __launch_bounds__(256, 1) void g2w(
    int Kd,
    const __nv_bfloat16* __restrict__ Ah, const __nv_bfloat16* __restrict__ Al, int lda,
    const __nv_bfloat16* __restrict__ Bh, const __nv_bfloat16* __restrict__ Bl, int ldb,
    __nv_bfloat16* __restrict__ Ch, __nv_bfloat16* __restrict__ Cl,
    int ldc, const float* __restrict__ bias)
{
    constexpr int STAGE = 49152;   // Ah 16K | Al 16K | Bh 8K | Bl 8K
    extern __shared__ char dsm[];

    const int tid = threadIdx.x, wid = tid >> 5, lane = tid & 31;
    const int row0 = blockIdx.y * 256, col0 = blockIdx.x * 128;
    const int warpM = (wid >> 1) * 64, warpN = (wid & 1) * 64;

    uint32_t sbase = (smem_u32(dsm) + 1023) & ~1023u;

    float acc[4][8][4];
    #pragma unroll
    for (int a = 0; a < 4; a++)
        #pragma unroll
        for (int b = 0; b < 8; b++)
            #pragma unroll
            for (int c = 0; c < 4; c++) acc[a][b][c] = 0.f;

    auto LOADST = [&](int st, int kt) {
        uint32_t sa = sbase + st * STAGE;
        // A: 256 rows x 32 bf16 (64B/row)
        #pragma unroll
        for (int i = 0; i < 4; i++) {
            int cid = tid + 256 * i;
            int r = cid >> 2, c = cid & 3;
            size_t go = (size_t)(row0 + r) * lda + kt * 32 + c * 8;
            uint32_t so = (uint32_t)(r * 64 + ((c ^ ((r >> 1) & 3)) << 4));
            cpa16(sa + so, Ah + go);
            cpa16(sa + 16384 + so, Al + go);
        }
        // B: 32 rows x 128 bf16 (256B/row)
        #pragma unroll
        for (int i = 0; i < 2; i++) {
            int cid = tid + 256 * i;
            int r = cid >> 4, c = cid & 15;
            size_t go = (size_t)(kt * 32 + r) * ldb + col0 + c * 8;
            uint32_t cs = (uint32_t)((c & 8) | ((c & 7) ^ (r & 7)));
            uint32_t so = (uint32_t)(r * 256 + (cs << 4));
            cpa16(sa + 32768 + so, Bh + go);
            cpa16(sa + 40960 + so, Bl + go);
        }
    };

    auto COMP = [&](int st) {
        uint32_t sa = sbase + st * STAGE;
        uint32_t sAl_ = sa + 16384, sBh_ = sa + 32768, sBl_ = sBh_ + 8192;
        #pragma unroll
        for (int ks = 0; ks < 2; ks++) {
            uint32_t bhf[4][4], blf[4][4];
            #pragma unroll
            for (int g = 0; g < 4; g++) {
                int idx = lane & 7, sel = lane >> 3;
                int k = ks * 16 + (sel & 1) * 8 + idx;
                int c = ((warpN + g * 16) >> 3) + (sel >> 1);
                uint32_t cs = (uint32_t)((c & 8) | ((c & 7) ^ (k & 7)));
                uint32_t so = (uint32_t)(k * 256 + (cs << 4));
                ldm4t(bhf[g], sBh_ + so);
                ldm4t(blf[g], sBl_ + so);
            }
            #pragma unroll
            for (int mf = 0; mf < 4; mf++) {
                uint32_t ahf[4], alf[4];
                int r = warpM + mf * 16 + (lane & 15);
                int ch = ks * 2 + (lane >> 4);
                uint32_t so = (uint32_t)(r * 64 + ((ch ^ ((r >> 1) & 3)) << 4));
                ldm4(ahf, sa + so);
                ldm4(alf, sAl_ + so);
                #pragma unroll
                for (int nf = 0; nf < 8; nf++) {
                    int g = nf >> 1;
                    uint32_t bh[2] = { bhf[g][(nf & 1) * 2], bhf[g][(nf & 1) * 2 + 1] };
                    uint32_t bl[2] = { blf[g][(nf & 1) * 2], blf[g][(nf & 1) * 2 + 1] };
                    mma16816(acc[mf][nf], ahf, bh);
                    mma16816(acc[mf][nf], alf, bh);
                    mma16816(acc[mf][nf], ahf, bl);
                }
            }
        }
    };

    const int nt = Kd / 32;
    LOADST(0, 0); CPA_COMMIT();
    if (nt > 1) { LOADST(1, 1); CPA_COMMIT(); }
    for (int kt = 0; kt < nt; kt++) {
        if (kt + 1 < nt) cpa_wait1(); else cpa_wait0();
        __syncthreads();
        if (kt + 2 < nt) { LOADST((kt + 2) % 3, kt + 2); CPA_COMMIT(); }
        COMP(kt % 3);
    }

    #pragma unroll
    for (int mf = 0; mf < 4; mf++)
        #pragma unroll
        for (int nf = 0; nf < 8; nf++) {
            int r = row0 + warpM + mf * 16 + (lane >> 2);
            int c = col0 + warpN + nf * 8 + (lane & 3) * 2;
            float b0 = 0.f, b1 = 0.f;
            if (bias) { b0 = bias[c]; b1 = bias[c + 1]; }
            float v0 = acc[mf][nf][0] + b0, v1 = acc[mf][nf][1] + b1;
            float v2 = acc[mf][nf][2] + b0, v3 = acc[mf][nf][3] + b1;
            if (EPI & 1) { v0 = gelu_f(v0); v1 = gelu_f(v1); v2 = gelu_f(v2); v3 = gelu_f(v3); }
            __nv_bfloat16 h0, h1, h2, h3, l0, l1, l2, l3;
            split1(v0, h0, l0); split1(v1, h1, l1);
            split1(v2, h2, l2); split1(v3, h3, l3);
            *(uint32_t*)&Ch[(size_t)r * ldc + c]       = packbf2(h0, h1);
            *(uint32_t*)&Cl[(size_t)r * ldc + c]       = packbf2(l0, l1);
            *(uint32_t*)&Ch[(size_t)(r + 8) * ldc + c] = packbf2(h2, h3);
            *(uint32_t*)&Cl[(size_t)(r + 8) * ldc + c] = packbf2(l2, l3);
        }
}

// =================================================================================
// Fused attention: per CTA = (batch*head, 128-query block). KV tile = 64 keys.
// =================================================================================
__global__ __launch_bounds__(256, 2) void flash_kernel(
    const __nv_bfloat16* __restrict__ qkvh, const __nv_bfloat16* __restrict__ qkvl,
    const int* __restrict__ am,
    __nv_bfloat16* __restrict__ ctxh, __nv_bfloat16* __restrict__ ctxl)
{
    extern __shared__ char dsm[];
    const int tid = threadIdx.x, wid = tid >> 5, lane = tid & 31;
    const int qb = blockIdx.x;                 // 0..3
    const int bh = blockIdx.y;                 // 0..191
    const int b = bh / NHH, h = bh - b * NHH;

    uint32_t sbu  = smem_u32(dsm);
    uint32_t base = (sbu + 1023) & ~1023u;
    char*    bp   = dsm + (base - sbu);
    const uint32_t QH = 0, QL = 16384;
    const uint32_t KV = 32768;                 // stage stride 32768: KH|KL|VH|VL 8KB each
    const uint32_t AMS = 98304;                // 512 floats

    const size_t tokq = (size_t)b * SS + qb * 128;

    for (int i = tid; i < SS; i += 256)
        *(float*)(bp + AMS + i * 4) = am[b * SS + i] ? 0.f : -1e4f;

    #pragma unroll
    for (int i = 0; i < 4; i++) {
        int cid = tid + 256 * i;
        int r = cid >> 3, c = cid & 7;
        size_t go = (tokq + r) * H3 + h * DHH + c * 8;
        uint32_t so = (uint32_t)(r * 128 + ((c ^ (r & 7)) << 4));
        cpa16(base + QH + so, qkvh + go);
        cpa16(base + QL + so, qkvl + go);
    }
    auto LOADKV = [&](int st, int kb) {
        uint32_t sk = base + KV + st * 32768;
        #pragma unroll
        for (int i = 0; i < 2; i++) {
            int cid = tid + 256 * i;
            int r = cid >> 3, c = cid & 7;
            size_t gk = ((size_t)b * SS + kb * 64 + r) * H3 + HH + h * DHH + c * 8;
            size_t gv = gk + HH;
            uint32_t so = (uint32_t)(r * 128 + ((c ^ (r & 7)) << 4));
            cpa16(sk + so,         qkvh + gk);
            cpa16(sk + 8192 + so,  qkvl + gk);
            cpa16(sk + 16384 + so, qkvh + gv);
            cpa16(sk + 24576 + so, qkvl + gv);
        }
    };

    LOADKV(0, 0); CPA_COMMIT();

    float oacc[8][4];
    #pragma unroll
    for (int i = 0; i < 8; i++)
        #pragma unroll
        for (int j = 0; j < 4; j++) oacc[i][j] = 0.f;
    float m0 = -1e30f, m1 = -1e30f, l0 = 0.f, l1 = 0.f;

    for (int kb = 0; kb < 8; kb++) {
        bool more = (kb < 7);
        if (more) { LOADKV((kb + 1) & 1, kb + 1); CPA_COMMIT(); }
        if (more) cpa_wait1(); else cpa_wait0();
        __syncthreads();

        uint32_t stg = base + KV + (kb & 1) * 32768;
        float sacc[8][4];
        #pragma unroll
        for (int i = 0; i < 8; i++)
            #pragma unroll
            for (int j = 0; j < 4; j++) sacc[i][j] = 0.f;

        // ---- S = Q @ K^T  (128q x 64k) ----
        #pragma unroll
        for (int ks = 0; ks < 4; ks++) {
            uint32_t qhf[4], qlf[4];
            {
                int r = wid * 16 + (lane & 15);
                uint32_t so = (uint32_t)(r * 128 + (((ks * 2 + (lane >> 4)) ^ (r & 7)) << 4));
                ldm4(qhf, base + QH + so);
                ldm4(qlf, base + QL + so);
            }
            uint32_t khf[4][4], klf[4][4];
            #pragma unroll
            for (int g = 0; g < 4; g++) {
                int n = g * 16 + (lane & 15);
                uint32_t so = (uint32_t)(n * 128 + (((ks * 2 + (lane >> 4)) ^ (n & 7)) << 4));
                ldm4(khf[g], stg + so);
                ldm4(klf[g], stg + 8192 + so);
            }
            #pragma unroll
            for (int nf = 0; nf < 8; nf++) {
                int g = nf >> 1;
                uint32_t bh2[2] = { khf[g][nf & 1], khf[g][2 + (nf & 1)] };
                uint32_t bl2[2] = { klf[g][nf & 1], klf[g][2 + (nf & 1)] };
                mma16816(sacc[nf], qhf, bh2);
                mma16816(sacc[nf], qlf, bh2);
                mma16816(sacc[nf], qhf, bl2);
            }
        }

        // ---- online softmax ----
        float vmax0 = -1e30f, vmax1 = -1e30f;
        #pragma unroll
        for (int nf = 0; nf < 8; nf++) {
            int col = kb * 64 + nf * 8 + (lane & 3) * 2;
            float b0 = *(const float*)(bp + AMS + col * 4);
            float b1 = *(const float*)(bp + AMS + (col + 1) * 4);
            sacc[nf][0] = sacc[nf][0] * 0.125f + b0;
            sacc[nf][1] = sacc[nf][1] * 0.125f + b1;
            sacc[nf][2] = sacc[nf][2] * 0.125f + b0;
            sacc[nf][3] = sacc[nf][3] * 0.125f + b1;
            vmax0 = fmaxf(vmax0, fmaxf(sacc[nf][0], sacc[nf][1]));
            vmax1 = fmaxf(vmax1, fmaxf(sacc[nf][2], sacc[nf][3]));
        }
        vmax0 = fmaxf(vmax0, __shfl_xor_sync(0xffffffffu, vmax0, 1));
        vmax0 = fmaxf(vmax0, __shfl_xor_sync(0xffffffffu, vmax0, 2));
        vmax1 = fmaxf(vmax1, __shfl_xor_sync(0xffffffffu, vmax1, 1));
        vmax1 = fmaxf(vmax1, __shfl_xor_sync(0xffffffffu, vmax1, 2));
        float mn0 = fmaxf(m0, vmax0), mn1 = fmaxf(m1, vmax1);
        float f0 = __expf(m0 - mn0), f1 = __expf(m1 - mn1);
        float rs0 = 0.f, rs1 = 0.f;
        #pragma unroll
        for (int nf = 0; nf < 8; nf++) {
            sacc[nf][0] = __expf(sacc[nf][0] - mn0);
            sacc[nf][1] = __expf(sacc[nf][1] - mn0);
            sacc[nf][2] = __expf(sacc[nf][2] - mn1);
            sacc[nf][3] = __expf(sacc[nf][3] - mn1);
            rs0 += sacc[nf][0] + sacc[nf][1];
            rs1 += sacc[nf][2] + sacc[nf][3];
        }
        rs0 += __shfl_xor_sync(0xffffffffu, rs0, 1);
        rs0 += __shfl_xor_sync(0xffffffffu, rs0, 2);
        rs1 += __shfl_xor_sync(0xffffffffu, rs1, 1);
        rs1 += __shfl_xor_sync(0xffffffffu, rs1, 2);
        l0 = l0 * f0 + rs0;
        l1 = l1 * f1 + rs1;
        m0 = mn0; m1 = mn1;
        #pragma unroll
        for (int onf = 0; onf < 8; onf++) {
            oacc[onf][0] *= f0; oacc[onf][1] *= f0;
            oacc[onf][2] *= f1; oacc[onf][3] *= f1;
        }

        // ---- O += P @ V ----
        #pragma unroll
        for (int kp = 0; kp < 4; kp++) {
            uint32_t pph[4], ppl[4];
            {
                int nf0 = 2 * kp, nf1 = 2 * kp + 1;
                __nv_bfloat16 h0, h1, h2, h3, u0, u1, u2, u3;
                split1(sacc[nf0][0], h0, u0); split1(sacc[nf0][1], h1, u1);
                split1(sacc[nf0][2], h2, u2); split1(sacc[nf0][3], h3, u3);
                pph[0] = packbf2(h0, h1); ppl[0] = packbf2(u0, u1);
                pph[1] = packbf2(h2, h3); ppl[1] = packbf2(u2, u3);
                split1(sacc[nf1][0], h0, u0); split1(sacc[nf1][1], h1, u1);
                split1(sacc[nf1][2], h2, u2); split1(sacc[nf1][3], h3, u3);
                pph[2] = packbf2(h0, h1); ppl[2] = packbf2(u0, u1);
                pph[3] = packbf2(h2, h3); ppl[3] = packbf2(u2, u3);
            }
            uint32_t vhf[4][4], vlf[4][4];
            #pragma unroll
            for (int g = 0; g < 4; g++) {
                int idx = lane & 7, sel = lane >> 3;
                int k = kp * 16 + (sel & 1) * 8 + idx;
                int c = 2 * g + (sel >> 1);
                uint32_t so = (uint32_t)(k * 128 + ((c ^ (k & 7)) << 4));
                ldm4t(vhf[g], stg + 16384 + so);
                ldm4t(vlf[g], stg + 24576 + so);
            }
            #pragma unroll
            for (int onf = 0; onf < 8; onf++) {
                int g = onf >> 1;
                uint32_t vh2[2] = { vhf[g][(onf & 1) * 2], vhf[g][(onf & 1) * 2 + 1] };
                uint32_t vl2[2] = { vlf[g][(onf & 1) * 2], vlf[g][(onf & 1) * 2 + 1] };
                mma16816(oacc[onf], pph, vh2);
                mma16816(oacc[onf], ppl, vh2);
                mma16816(oacc[onf], pph, vl2);
            }
        }
        __syncthreads();
    }

    float il0 = 1.f / l0, il1 = 1.f / l1;
    size_t tok = tokq + wid * 16 + (lane >> 2);
    #pragma unroll
    for (int onf = 0; onf < 8; onf++) {
        int c = h * DHH + onf * 8 + (lane & 3) * 2;
        float v0 = oacc[onf][0] * il0, v1 = oacc[onf][1] * il0;
        float v2 = oacc[onf][2] * il1, v3 = oacc[onf][3] * il1;
        __nv_bfloat16 h0, h1, h2, h3, u0, u1, u2, u3;
        split1(v0, h0, u0); split1(v1, h1, u1);
        split1(v2, h2, u2); split1(v3, h3, u3);
        *(uint32_t*)&ctxh[tok * HH + c]       = packbf2(h0, h1);
        *(uint32_t*)&ctxl[tok * HH + c]       = packbf2(u0, u1);
        *(uint32_t*)&ctxh[(tok + 8) * HH + c] = packbf2(h2, h3);
        *(uint32_t*)&ctxl[(tok + 8) * HH + c] = packbf2(u2, u3);
    }
}

// ---------------- weight split: fp32 -> bf16 hi/lo ----------------
__global__ __launch_bounds__(256) void wsplit(
    const float4* __restrict__ w, __nv_bfloat162* __restrict__ h,
    __nv_bfloat162* __restrict__ l, int n4)
{
    int i = blockIdx.x * 256 + threadIdx.x;
    if (i >= n4) return;
    float4 v = w[i];
    __nv_bfloat16 h0, h1, h2, h3, l0, l1, l2, l3;
    split1(v.x, h0, l0); split1(v.y, h1, l1);
    split1(v.z, h2, l2); split1(v.w, h3, l3);
    __nv_bfloat162 a; a.x = h0; a.y = h1;
    __nv_bfloat162 b; b.x = h2; b.y = h3;
    __nv_bfloat162 c; c.x = l0; c.y = l1;
    __nv_bfloat162 d; d.x = l2; d.y = l3;
    h[i * 2] = a; h[i * 2 + 1] = b;
    l[i * 2] = c; l[i * 2 + 1] = d;
}

// ---------------- embedding + LayerNorm (+ split), float4-vectorized ----------------
__global__ __launch_bounds__(256) void embed_ln_kernel(
    const int* __restrict__ ids, const float* __restrict__ tok,
    const float* __restrict__ pos, const float* __restrict__ gs,
    const float* __restrict__ gb, float* __restrict__ out,
    __nv_bfloat16* __restrict__ oh, __nv_bfloat16* __restrict__ ol)
{
    int t  = blockIdx.x;
    int sp = t & (SS - 1);
    int id = ids[t];
    int j  = threadIdx.x;           // 0..255; active j<192 (768/4)
    float4 v4 = make_float4(0.f, 0.f, 0.f, 0.f);
    if (j < HH / 4) {
        float4 a = *(const float4*)&tok[(size_t)id * HH + j * 4];
        float4 p = *(const float4*)&pos[(size_t)sp * HH + j * 4];
        v4 = make_float4(a.x + p.x, a.y + p.y, a.z + p.z, a.w + p.w);
    }
    float s = v4.x + v4.y + v4.z + v4.w;
    float mean = block_sum_256(s) * (1.f / HH);
    float sq = 0.f;
    if (j < HH / 4) {
        float d0 = v4.x - mean, d1 = v4.y - mean, d2 = v4.z - mean, d3 = v4.w - mean;
        sq = d0 * d0 + d1 * d1 + d2 * d2 + d3 * d3;
    }
    float var = block_sum_256(sq) * (1.f / HH);
    float inv = rsqrtf(var + 1e-12f);
    if (j < HH / 4) {
        float4 g4 = *(const float4*)&gs[j * 4];
        float4 b4 = *(const float4*)&gb[j * 4];
        float r0 = (v4.x - mean) * inv * g4.x + b4.x;
        float r1 = (v4.y - mean) * inv * g4.y + b4.y;
        float r2 = (v4.z - mean) * inv * g4.z + b4.z;
        float r3 = (v4.w - mean) * inv * g4.w + b4.w;
        *(float4*)&out[(size_t)t * HH + j * 4] = make_float4(r0, r1, r2, r3);
        __nv_bfloat16 h0, h1, h2, h3, l0, l1, l2, l3;
        split1(r0, h0, l0); split1(r1, h1, l1);
        split1(r2, h2, l2); split1(r3, h3, l3);
        *(uint32_t*)&oh[(size_t)t * HH + j * 4]     = packbf2(h0, h1);
        *(uint32_t*)&oh[(size_t)t * HH + j * 4 + 2] = packbf2(h2, h3);
        *(uint32_t*)&ol[(size_t)t * HH + j * 4]     = packbf2(l0, l1);
        *(uint32_t*)&ol[(size_t)t * HH + j * 4 + 2] = packbf2(l2, l3);
    }
}

// ---------------- LayerNorm of (tmp + tmp2) -> x + split, float4-vectorized ----------------
__global__ __launch_bounds__(256) void ln_split2_kernel(
    const float* __restrict__ t_in, const float* __restrict__ t_in2,
    float* __restrict__ x,
    const float* __restrict__ gs, const float* __restrict__ gb,
    __nv_bfloat16* __restrict__ oh, __nv_bfloat16* __restrict__ ol)
{
    int t = blockIdx.x;
    int j = threadIdx.x;
    float4 v4 = make_float4(0.f, 0.f, 0.f, 0.f);
    if (j < HH / 4) {
        float4 a = *(const float4*)&t_in[(size_t)t * HH + j * 4];
        float4 b = *(const float4*)&t_in2[(size_t)t * HH + j * 4];
        v4 = make_float4(a.x + b.x, a.y + b.y, a.z + b.z, a.w + b.w);
    }
    float s = v4.x + v4.y + v4.z + v4.w;
    float mean = block_sum_256(s) * (1.f / HH);
    float sq = 0.f;
    if (j < HH / 4) {
        float d0 = v4.x - mean, d1 = v4.y - mean, d2 = v4.z - mean, d3 = v4.w - mean;
        sq = d0 * d0 + d1 * d1 + d2 * d2 + d3 * d3;
    }
    float var = block_sum_256(sq) * (1.f / HH);
    float inv = rsqrtf(var + 1e-12f);
    if (j < HH / 4) {
        float4 g4 = *(const float4*)&gs[j * 4];
        float4 b4 = *(const float4*)&gb[j * 4];
        float r0 = (v4.x - mean) * inv * g4.x + b4.x;
        float r1 = (v4.y - mean) * inv * g4.y + b4.y;
        float r2 = (v4.z - mean) * inv * g4.z + b4.z;
        float r3 = (v4.w - mean) * inv * g4.w + b4.w;
        *(float4*)&x[(size_t)t * HH + j * 4] = make_float4(r0, r1, r2, r3);
        __nv_bfloat16 h0, h1, h2, h3, l0, l1, l2, l3;
        split1(r0, h0, l0); split1(r1, h1, l1);
        split1(r2, h2, l2); split1(r3, h3, l3);
        *(uint32_t*)&oh[(size_t)t * HH + j * 4]     = packbf2(h0, h1);
        *(uint32_t*)&oh[(size_t)t * HH + j * 4 + 2] = packbf2(h2, h3);
        *(uint32_t*)&ol[(size_t)t * HH + j * 4]     = packbf2(l0, l1);
        *(uint32_t*)&ol[(size_t)t * HH + j * 4 + 2] = packbf2(l2, l3);
    }
}

// ---------------- small SIMT GEMM (classifier, N=9) ----------------
__global__ __launch_bounds__(256) void cls_gemm_kernel(
    const float* __restrict__ A, const float* __restrict__ B,
    const float* __restrict__ bias, float* __restrict__ C)
{
    int row = blockIdx.x * 8 + (threadIdx.x >> 5);
    int lane = threadIdx.x & 31;
    if (row >= TOK) return;
    const float* a = A + (size_t)row * HH;
    float acc[KK];
    #pragma unroll
    for (int j = 0; j < KK; j++) acc[j] = 0.f;
    for (int k = lane; k < HH; k += 32) {
        float av = a[k];
        const float* bp = B + (size_t)k * KK;
        #pragma unroll
        for (int j = 0; j < KK; j++) acc[j] += av * bp[j];
    }
    #pragma unroll
    for (int j = 0; j < KK; j++) {
        float s = warp_sum(acc[j]);
        if (lane == 0) C[(size_t)row * KK + j] = s + bias[j];
    }
}

// ---------------- CRF NLL (single block) ----------------
__global__ __launch_bounds__(256) void crf_kernel(
    const float* __restrict__ emis, const int* __restrict__ labels,
    const int* __restrict__ am, const float* __restrict__ cs,
    const float* __restrict__ ce, const float* __restrict__ ct,
    float* __restrict__ loss_out)
{
    __shared__ float alpha[BB][KK];
    __shared__ float trans[KK][KK];
    __shared__ float den[BB];
    __shared__ float num[BB];

    int tid = threadIdx.x;
    if (tid < KK * KK) trans[tid / KK][tid % KK] = ct[tid];
    __syncthreads();

    int b = tid / KK, j = tid - b * KK;
    bool act = tid < BB * KK;
    if (act) alpha[b][j] = cs[j] + emis[(size_t)(b * SS) * KK + j];
    __syncthreads();

    for (int s = 1; s < SS; s++) {
        float nv = 0.f;
        if (act) {
            int idx = b * SS + s;
            bool m = (labels[idx] != -100) && (am[idx] == 1);
            if (m) {
                float mx = -1e30f;
                #pragma unroll
                for (int i = 0; i < KK; i++) mx = fmaxf(mx, alpha[b][i] + trans[i][j]);
                float sum = 0.f;
                #pragma unroll
                for (int i = 0; i < KK; i++) sum += expf(alpha[b][i] + trans[i][j] - mx);
                nv = mx + logf(sum) + emis[(size_t)idx * KK + j];
            } else {
                nv = alpha[b][j];
            }
        }
        __syncthreads();
        if (act) alpha[b][j] = nv;
        __syncthreads();
    }

    if (act && j == 0) {
        float mx = -1e30f;
        #pragma unroll
        for (int i = 0; i < KK; i++) mx = fmaxf(mx, alpha[b][i] + ce[i]);
        float sum = 0.f;
        #pragma unroll
        for (int i = 0; i < KK; i++) sum += expf(alpha[b][i] + ce[i] - mx);
        den[b] = mx + logf(sum);
    }

    if (tid < BB) {
        int bb = tid;
        int l0 = labels[bb * SS];
        int t0 = (l0 == -100) ? 0 : l0;
        float sc = cs[t0] + emis[(size_t)(bb * SS) * KK + t0];
        int prev = t0;
        int cnt = 1;
        for (int s = 1; s < SS; s++) {
            int idx = bb * SS + s;
            int l = labels[idx];
            bool m = (l != -100) && (am[idx] == 1);
            int tg = (l == -100) ? 0 : l;
            if (m) {
                sc += trans[prev][tg] + emis[(size_t)idx * KK + tg];
                cnt++;
            }
            prev = tg;
        }
        int li = cnt - 1;
        int ll = labels[bb * SS + li];
        int lt = (ll == -100) ? 0 : ll;
        sc += ce[lt];
        num[bb] = sc;
    }
    __syncthreads();
    if (tid == 0) {
        float L = 0.f;
        for (int i = 0; i < BB; i++) L += num[i] - den[i];
        loss_out[0] = -(L / (float)BB);
    }
}

// ---------------- launch ----------------
extern "C" void kernel_launch(void* const* d_in, const int* in_sizes, int n_in,
                              void* d_out, int out_size)
{
    const int*   ids  = (const int*)d_in[0];
    const int*   am   = (const int*)d_in[1];
    const int*   lab  = (const int*)d_in[2];
    const float* etok = (const float*)d_in[3];
    const float* epos = (const float*)d_in[4];
    const float* elns = (const float*)d_in[5];
    const float* elnb = (const float*)d_in[6];
    const float* Wqkv = (const float*)d_in[7];
    const float* bqkv = (const float*)d_in[8];
    const float* Wo   = (const float*)d_in[9];
    const float* bo   = (const float*)d_in[10];
    const float* l1s  = (const float*)d_in[11];
    const float* l1b  = (const float*)d_in[12];
    const float* W1   = (const float*)d_in[13];
    const float* b1   = (const float*)d_in[14];
    const float* W2   = (const float*)d_in[15];
    const float* b2   = (const float*)d_in[16];
    const float* l2s  = (const float*)d_in[17];
    const float* l2b  = (const float*)d_in[18];
    const float* clsW = (const float*)d_in[19];
    const float* clsb = (const float*)d_in[20];
    const float* c_s  = (const float*)d_in[21];
    const float* c_e  = (const float*)d_in[22];
    const float* c_t  = (const float*)d_in[23];

    float *x, *tmp, *tmp2, *emis_s, *loss_s;
    __nv_bfloat16 *xh, *xl, *qkvh, *qkvl, *ffh, *ffl, *ctxh, *ctxl;
    __nv_bfloat16 *wqkvh, *wqkvl, *woh, *wol, *w1h, *w1l, *w2h, *w2l;
    cudaGetSymbolAddress((void**)&x,      g_x);
    cudaGetSymbolAddress((void**)&tmp,    g_tmp);
    cudaGetSymbolAddress((void**)&tmp2,   g_tmp2);
    cudaGetSymbolAddress((void**)&emis_s, g_emis);
    cudaGetSymbolAddress((void**)&loss_s, g_loss);
    cudaGetSymbolAddress((void**)&xh,     g_xh);
    cudaGetSymbolAddress((void**)&xl,     g_xl);
    cudaGetSymbolAddress((void**)&qkvh,   g_qkvh);
    cudaGetSymbolAddress((void**)&qkvl,   g_qkvl);
    cudaGetSymbolAddress((void**)&ffh,    g_ffh);
    cudaGetSymbolAddress((void**)&ffl,    g_ffl);
    cudaGetSymbolAddress((void**)&ctxh,   g_ctxh);
    cudaGetSymbolAddress((void**)&ctxl,   g_ctxl);
    cudaGetSymbolAddress((void**)&wqkvh,  g_wqkvh);
    cudaGetSymbolAddress((void**)&wqkvl,  g_wqkvl);
    cudaGetSymbolAddress((void**)&woh,    g_woh);
    cudaGetSymbolAddress((void**)&wol,    g_wol);
    cudaGetSymbolAddress((void**)&w1h,    g_w1h);
    cudaGetSymbolAddress((void**)&w1l,    g_w1l);
    cudaGetSymbolAddress((void**)&w2h,    g_w2h);
    cudaGetSymbolAddress((void**)&w2l,    g_w2l);

    const int EMIS = TOK * KK;
    float* out = (float*)d_out;
    float* emis_dst;
    float* loss_dst;
    if (out_size == EMIS + 1)      { loss_dst = out; emis_dst = out + 1; }
    else if (out_size == EMIS)     { loss_dst = loss_s; emis_dst = out; }
    else                           { loss_dst = out; emis_dst = emis_s; }

    const int SMG  = 3 * 32768 + 1024;       // g2: 97 KB -> 2 CTAs/SM
    const int SMGW = 3 * 49152 + 1024;       // g2w: 145 KB -> 1 CTA/SM
    const int SMFA = 1024 + 98304 + 2048;    // flash: ~100 KB -> 2 CTAs/SM
    cudaFuncSetAttribute(g2<12>, cudaFuncAttributeMaxDynamicSharedMemorySize, SMG);
    cudaFuncSetAttribute(g2w<2>, cudaFuncAttributeMaxDynamicSharedMemorySize, SMGW);
    cudaFuncSetAttribute(g2w<3>, cudaFuncAttributeMaxDynamicSharedMemorySize, SMGW);
    cudaFuncSetAttribute(flash_kernel, cudaFuncAttributeMaxDynamicSharedMemorySize, SMFA);

    // ---- one-time (per launch) weight splits ----
    {
        int n4;
        n4 = LL * HH * H3 / 4;
        wsplit<<<(n4 + 255) / 256, 256>>>((const float4*)Wqkv, (__nv_bfloat162*)wqkvh, (__nv_bfloat162*)wqkvl, n4);
        n4 = LL * HH * HH / 4;
        wsplit<<<(n4 + 255) / 256, 256>>>((const float4*)Wo,   (__nv_bfloat162*)woh,   (__nv_bfloat162*)wol,   n4);
        n4 = LL * HH * FFD / 4;
        wsplit<<<(n4 + 255) / 256, 256>>>((const float4*)W1,   (__nv_bfloat162*)w1h,   (__nv_bfloat162*)w1l,   n4);
        n4 = LL * FFD * HH / 4;
        wsplit<<<(n4 + 255) / 256, 256>>>((const float4*)W2,   (__nv_bfloat162*)w2h,   (__nv_bfloat162*)w2l,   n4);
    }

    embed_ln_kernel<<<TOK, 256>>>(ids, etok, epos, elns, elnb, x, xh, xl);

    for (int l = 0; l < LL; l++) {
        const float* bqkv_l = bqkv + (size_t)l * H3;
        const float* bo_l   = bo   + (size_t)l * HH;
        const float* l1s_l  = l1s  + (size_t)l * HH;
        const float* l1b_l  = l1b  + (size_t)l * HH;
        const float* b1_l   = b1   + (size_t)l * FFD;
        const float* b2_l   = b2   + (size_t)l * HH;
        const float* l2s_l  = l2s  + (size_t)l * HH;
        const float* l2b_l  = l2b  + (size_t)l * HH;
        const __nv_bfloat16* wqkvh_l = wqkvh + (size_t)l * HH * H3;
        const __nv_bfloat16* wqkvl_l = wqkvl + (size_t)l * HH * H3;
        const __nv_bfloat16* woh_l   = woh   + (size_t)l * HH * HH;
        const __nv_bfloat16* wol_l   = wol   + (size_t)l * HH * HH;
        const __nv_bfloat16* w1h_l   = w1h   + (size_t)l * HH * FFD;
        const __nv_bfloat16* w1l_l   = w1l   + (size_t)l * HH * FFD;
        const __nv_bfloat16* w2h_l   = w2h   + (size_t)l * FFD * HH;
        const __nv_bfloat16* w2l_l   = w2l   + (size_t)l * FFD * HH;

        // qkv = x @ Wqkv + bqkv  -> split   [8192,2304], K=768  (wide 256-row tile)
        g2w<2><<<dim3(H3 / 128, TOK / 256), 256, SMGW>>>(
            HH, xh, xl, HH, wqkvh_l, wqkvl_l, H3,
            qkvh, qkvl, H3, bqkv_l);

        // fused attention -> ctx hi/lo
        flash_kernel<<<dim3(SS / 128, BB * NHH), 256, SMFA>>>(qkvh, qkvl, am, ctxh, ctxl);

        // tmp(+tmp2) = x + ctx @ Wo + bo   split-K=2, [8192,768], K=2x384
        g2<12><<<dim3(HH / 128, TOK / 128, 2), 256, SMG>>>(
            HH / 2, ctxh, ctxl, HH, woh_l, wol_l, HH,
            tmp, nullptr, nullptr, HH, bo_l, x, tmp2);
        ln_split2_kernel<<<TOK, 256>>>(tmp, tmp2, x, l1s_l, l1b_l, xh, xl);

        // ff = gelu(x @ W1 + b1)  -> split   [8192,3072], K=768  (wide 256-row tile)
        g2w<3><<<dim3(FFD / 128, TOK / 256), 256, SMGW>>>(
            HH, xh, xl, HH, w1h_l, w1l_l, FFD,
            ffh, ffl, FFD, b1_l);

        // tmp(+tmp2) = x + ff @ W2 + b2   split-K=2, [8192,768], K=2x1536
        g2<12><<<dim3(HH / 128, TOK / 128, 2), 256, SMG>>>(
            FFD / 2, ffh, ffl, FFD, w2h_l, w2l_l, HH,
            tmp, nullptr, nullptr, HH, b2_l, x, tmp2);
        ln_split2_kernel<<<TOK, 256>>>(tmp, tmp2, x, l2s_l, l2b_l, xh, xl);
    }

    // emissions = x @ cls_W + cls_b   [8192, 9]
    cls_gemm_kernel<<<TOK / 8, 256>>>(x, clsW, clsb, emis_dst);

    // CRF loss
    crf_kernel<<<1, 256>>>(emis_dst, lab, am, c_s, c_e, c_t, loss_dst);
}

// round 17
// speedup vs baseline: 1.0733x; 1.0733x over previous
#include <cuda_runtime.h>
#include <cuda_bf16.h>
#include <math.h>
#include <stdint.h>

// Problem constants
#define BB   16
#define SS   512
#define HH   768
#define LL   12
#define NHH  12
#define DHH  64
#define FFD  3072
#define KK   9
#define TOK  (BB*SS)          // 8192
#define H3   (3*HH)           // 2304

// ---------------- scratch (static device globals; no allocation) ----------------
__device__ __align__(16) float g_x[TOK*HH];
__device__ __align__(16) float g_tmp[TOK*HH];
__device__ __align__(16) float g_tmp2[TOK*HH];
__device__ __align__(16) float g_emis[TOK*KK];
__device__ float g_loss[1];

// bf16 hi/lo split arrays (operands for tensor-core GEMMs)
__device__ __align__(16) __nv_bfloat16 g_xh[TOK*HH],    g_xl[TOK*HH];
__device__ __align__(16) __nv_bfloat16 g_qkvh[TOK*H3],  g_qkvl[TOK*H3];
__device__ __align__(16) __nv_bfloat16 g_ffh[TOK*FFD],  g_ffl[TOK*FFD];
__device__ __align__(16) __nv_bfloat16 g_ctxh[TOK*HH],  g_ctxl[TOK*HH];
__device__ __align__(16) __nv_bfloat16 g_wqkvh[LL*HH*H3],  g_wqkvl[LL*HH*H3];
__device__ __align__(16) __nv_bfloat16 g_woh[LL*HH*HH],    g_wol[LL*HH*HH];
__device__ __align__(16) __nv_bfloat16 g_w1h[LL*HH*FFD],   g_w1l[LL*HH*FFD];
__device__ __align__(16) __nv_bfloat16 g_w2h[LL*FFD*HH],   g_w2l[LL*FFD*HH];

// ---------------- helpers ----------------
__device__ __forceinline__ float warp_sum(float v) {
    #pragma unroll
    for (int o = 16; o; o >>= 1) v += __shfl_xor_sync(0xffffffffu, v, o);
    return v;
}
__device__ __forceinline__ float warp_max(float v) {
    #pragma unroll
    for (int o = 16; o; o >>= 1) v = fmaxf(v, __shfl_xor_sync(0xffffffffu, v, o));
    return v;
}
__device__ float block_sum_256(float v) {
    __shared__ float red[8];
    __shared__ float total;
    int lane = threadIdx.x & 31, w = threadIdx.x >> 5;
    v = warp_sum(v);
    if (lane == 0) red[w] = v;
    __syncthreads();
    if (w == 0) {
        float x = (lane < 8) ? red[lane] : 0.f;
        x = warp_sum(x);
        if (lane == 0) total = x;
    }
    __syncthreads();
    float r = total;
    __syncthreads();
    return r;
}
__device__ __forceinline__ float gelu_f(float x) {
    return 0.5f * x * (1.f + erff(x * 0.7071067811865475f));
}
__device__ __forceinline__ void split1(float v, __nv_bfloat16& h, __nv_bfloat16& l) {
    h = __float2bfloat16(v);
    l = __float2bfloat16(v - __bfloat162float(h));
}

// ---------------- PTX primitives ----------------
__device__ __forceinline__ uint32_t smem_u32(const void* p) {
    uint32_t a;
    asm("{ .reg .u64 t; cvta.to.shared.u64 t, %1; cvt.u32.u64 %0, t; }" : "=r"(a) : "l"(p));
    return a;
}
__device__ __forceinline__ void mma16816(float* d, const uint32_t* a, const uint32_t* b) {
    asm volatile(
        "mma.sync.aligned.m16n8k16.row.col.f32.bf16.bf16.f32 "
        "{%0,%1,%2,%3},{%4,%5,%6,%7},{%8,%9},{%0,%1,%2,%3};"
        : "+f"(d[0]), "+f"(d[1]), "+f"(d[2]), "+f"(d[3])
        : "r"(a[0]), "r"(a[1]), "r"(a[2]), "r"(a[3]), "r"(b[0]), "r"(b[1]));
}
__device__ __forceinline__ void ldm4(uint32_t* r, uint32_t s) {
    asm volatile("ldmatrix.sync.aligned.m8n8.x4.shared.b16 {%0,%1,%2,%3}, [%4];"
        : "=r"(r[0]), "=r"(r[1]), "=r"(r[2]), "=r"(r[3]) : "r"(s));
}
__device__ __forceinline__ void ldm4t(uint32_t* r, uint32_t s) {
    asm volatile("ldmatrix.sync.aligned.m8n8.x4.trans.shared.b16 {%0,%1,%2,%3}, [%4];"
        : "=r"(r[0]), "=r"(r[1]), "=r"(r[2]), "=r"(r[3]) : "r"(s));
}
__device__ __forceinline__ void cpa16(uint32_t s, const void* g) {
    asm volatile("cp.async.cg.shared.global [%0], [%1], 16;" :: "r"(s), "l"(g));
}
#define CPA_COMMIT() asm volatile("cp.async.commit_group;" ::: "memory")
__device__ __forceinline__ void cpa_wait1() { asm volatile("cp.async.wait_group 1;" ::: "memory"); }
__device__ __forceinline__ void cpa_wait0() { asm volatile("cp.async.wait_group 0;" ::: "memory"); }
__device__ __forceinline__ uint32_t packbf2(__nv_bfloat16 a, __nv_bfloat16 b) {
    __nv_bfloat162 t; t.x = a; t.y = b;
    return *(uint32_t*)&t;
}

// =================================================================================
// bf16x3 tensor-core GEMM (dense linears), operands pre-split in gmem.
//   C[M,N] = (Ah+Al) @ (Bh+Bl) + bias [+ res]   (3-pass) ; B [K,N] -> ldmatrix.trans
// Block tile 128 x 128, K-tile 32, cp.async 3-stage pipeline -> 97KB -> 2 CTAs/SM.
// EPI: bit0 GELU, bit1 split-bf16 output, bit2 residual, bit3 split-K (grid.z=2).
// =================================================================================
template<int EPI>
__global__ __launch_bounds__(256, 2) void g2(
    int Kd,
    const __nv_bfloat16* __restrict__ Ah, const __nv_bfloat16* __restrict__ Al, int lda,
    const __nv_bfloat16* __restrict__ Bh, const __nv_bfloat16* __restrict__ Bl, int ldb,
    float* __restrict__ Cf, __nv_bfloat16* __restrict__ Ch, __nv_bfloat16* __restrict__ Cl,
    int ldc, const float* __restrict__ bias, const float* __restrict__ res,
    float* __restrict__ Cf2)
{
    constexpr int STAGE = 32768;   // Ah 8K | Al 8K | Bh 8K | Bl 8K
    extern __shared__ char dsm[];

    if (EPI & 8) {
        int z = blockIdx.z;
        Ah += (size_t)z * Kd;          Al += (size_t)z * Kd;
        Bh += (size_t)z * Kd * ldb;    Bl += (size_t)z * Kd * ldb;
    }

    const int tid = threadIdx.x, wid = tid >> 5, lane = tid & 31;
    const int row0 = blockIdx.y * 128, col0 = blockIdx.x * 128;
    const int warpM = (wid >> 1) * 32, warpN = (wid & 1) * 64;

    uint32_t sbase = (smem_u32(dsm) + 1023) & ~1023u;

    float acc[2][8][4];
    #pragma unroll
    for (int a = 0; a < 2; a++)
        #pragma unroll
        for (int b = 0; b < 8; b++)
            #pragma unroll
            for (int c = 0; c < 4; c++) acc[a][b][c] = 0.f;

    auto LOADST = [&](int st, int kt) {
        uint32_t sa = sbase + st * STAGE;
        #pragma unroll
        for (int i = 0; i < 2; i++) {
            int cid = tid + 256 * i;
            int r = cid >> 2, c = cid & 3;
            size_t go = (size_t)(row0 + r) * lda + kt * 32 + c * 8;
            uint32_t so = (uint32_t)(r * 64 + ((c ^ ((r >> 1) & 3)) << 4));
            cpa16(sa + so, Ah + go);
            cpa16(sa + 8192 + so, Al + go);
        }
        #pragma unroll
        for (int i = 0; i < 2; i++) {
            int cid = tid + 256 * i;
            int r = cid >> 4, c = cid & 15;
            size_t go = (size_t)(kt * 32 + r) * ldb + col0 + c * 8;
            uint32_t cs = (uint32_t)((c & 8) | ((c & 7) ^ (r & 7)));
            uint32_t so = (uint32_t)(r * 256 + (cs << 4));
            cpa16(sa + 16384 + so, Bh + go);
            cpa16(sa + 24576 + so, Bl + go);
        }
    };

    auto COMP = [&](int st) {
        uint32_t sa = sbase + st * STAGE;
        uint32_t sAl_ = sa + 8192, sBh_ = sa + 16384, sBl_ = sBh_ + 8192;
        #pragma unroll
        for (int ks = 0; ks < 2; ks++) {
            uint32_t ahf[2][4], alf[2][4];
            #pragma unroll
            for (int mf = 0; mf < 2; mf++) {
                int r = warpM + mf * 16 + (lane & 15);
                int ch = ks * 2 + (lane >> 4);
                uint32_t so = (uint32_t)(r * 64 + ((ch ^ ((r >> 1) & 3)) << 4));
                ldm4(ahf[mf], sa + so);
                ldm4(alf[mf], sAl_ + so);
            }
            uint32_t bhf[4][4], blf[4][4];
            #pragma unroll
            for (int g = 0; g < 4; g++) {
                int idx = lane & 7, sel = lane >> 3;
                int k = ks * 16 + (sel & 1) * 8 + idx;
                int c = ((warpN + g * 16) >> 3) + (sel >> 1);
                uint32_t cs = (uint32_t)((c & 8) | ((c & 7) ^ (k & 7)));
                uint32_t so = (uint32_t)(k * 256 + (cs << 4));
                ldm4t(bhf[g], sBh_ + so);
                ldm4t(blf[g], sBl_ + so);
            }
            #pragma unroll
            for (int mf = 0; mf < 2; mf++)
                #pragma unroll
                for (int nf = 0; nf < 8; nf++) {
                    int g = nf >> 1;
                    uint32_t bh[2] = { bhf[g][(nf & 1) * 2], bhf[g][(nf & 1) * 2 + 1] };
                    uint32_t bl[2] = { blf[g][(nf & 1) * 2], blf[g][(nf & 1) * 2 + 1] };
                    mma16816(acc[mf][nf], ahf[mf], bh);
                    mma16816(acc[mf][nf], alf[mf], bh);
                    mma16816(acc[mf][nf], ahf[mf], bl);
                }
        }
    };

    const int nt = Kd / 32;
    LOADST(0, 0); CPA_COMMIT();
    if (nt > 1) { LOADST(1, 1); CPA_COMMIT(); }
    for (int kt = 0; kt < nt; kt++) {
        if (kt + 1 < nt) cpa_wait1(); else cpa_wait0();
        __syncthreads();
        if (kt + 2 < nt) { LOADST((kt + 2) % 3, kt + 2); CPA_COMMIT(); }
        COMP(kt % 3);
    }

    const bool raw = (EPI & 8) && (blockIdx.z == 1);
    #pragma unroll
    for (int mf = 0; mf < 2; mf++)
        #pragma unroll
        for (int nf = 0; nf < 8; nf++) {
            int r = row0 + warpM + mf * 16 + (lane >> 2);
            int c = col0 + warpN + nf * 8 + (lane & 3) * 2;
            if (raw) {
                *(float2*)&Cf2[(size_t)r * ldc + c]       = make_float2(acc[mf][nf][0], acc[mf][nf][1]);
                *(float2*)&Cf2[(size_t)(r + 8) * ldc + c] = make_float2(acc[mf][nf][2], acc[mf][nf][3]);
                continue;
            }
            float b0 = 0.f, b1 = 0.f;
            if (bias) { b0 = bias[c]; b1 = bias[c + 1]; }
            float v0 = acc[mf][nf][0] + b0, v1 = acc[mf][nf][1] + b1;
            float v2 = acc[mf][nf][2] + b0, v3 = acc[mf][nf][3] + b1;
            if (EPI & 4) {
                float2 r0 = *(const float2*)&res[(size_t)r * ldc + c];
                float2 r1 = *(const float2*)&res[(size_t)(r + 8) * ldc + c];
                v0 += r0.x; v1 += r0.y; v2 += r1.x; v3 += r1.y;
            }
            if (EPI & 1) { v0 = gelu_f(v0); v1 = gelu_f(v1); v2 = gelu_f(v2); v3 = gelu_f(v3); }
            if (EPI & 2) {
                __nv_bfloat16 h0, h1, h2, h3, l0, l1, l2, l3;
                split1(v0, h0, l0); split1(v1, h1, l1);
                split1(v2, h2, l2); split1(v3, h3, l3);
                *(uint32_t*)&Ch[(size_t)r * ldc + c]       = packbf2(h0, h1);
                *(uint32_t*)&Cl[(size_t)r * ldc + c]       = packbf2(l0, l1);
                *(uint32_t*)&Ch[(size_t)(r + 8) * ldc + c] = packbf2(h2, h3);
                *(uint32_t*)&Cl[(size_t)(r + 8) * ldc + c] = packbf2(l2, l3);
            } else {
                *(float2*)&Cf[(size_t)r * ldc + c]       = make_float2(v0, v1);
                *(float2*)&Cf[(size_t)(r + 8) * ldc + c] = make_float2(v2, v3);
            }
        }
}

// =================================================================================
// Fused attention: per CTA = (batch*head, 128-query block). KV tile = 64 keys,
// smem ~100KB -> 2 CTAs/SM. 8 double-buffered KV steps, online softmax in regs.
// =================================================================================
__global__ __launch_bounds__(256, 2) void flash_kernel(
    const __nv_bfloat16* __restrict__ qkvh, const __nv_bfloat16* __restrict__ qkvl,
    const int* __restrict__ am,
    __nv_bfloat16* __restrict__ ctxh, __nv_bfloat16* __restrict__ ctxl)
{
    extern __shared__ char dsm[];
    const int tid = threadIdx.x, wid = tid >> 5, lane = tid & 31;
    const int qb = blockIdx.x;                 // 0..3
    const int bh = blockIdx.y;                 // 0..191
    const int b = bh / NHH, h = bh - b * NHH;

    uint32_t sbu  = smem_u32(dsm);
    uint32_t base = (sbu + 1023) & ~1023u;
    char*    bp   = dsm + (base - sbu);
    const uint32_t QH = 0, QL = 16384;
    const uint32_t KV = 32768;                 // stage stride 32768: KH|KL|VH|VL 8KB each
    const uint32_t AMS = 98304;                // 512 floats

    const size_t tokq = (size_t)b * SS + qb * 128;

    for (int i = tid; i < SS; i += 256)
        *(float*)(bp + AMS + i * 4) = am[b * SS + i] ? 0.f : -1e4f;

    #pragma unroll
    for (int i = 0; i < 4; i++) {
        int cid = tid + 256 * i;
        int r = cid >> 3, c = cid & 7;
        size_t go = (tokq + r) * H3 + h * DHH + c * 8;
        uint32_t so = (uint32_t)(r * 128 + ((c ^ (r & 7)) << 4));
        cpa16(base + QH + so, qkvh + go);
        cpa16(base + QL + so, qkvl + go);
    }
    auto LOADKV = [&](int st, int kb) {
        uint32_t sk = base + KV + st * 32768;
        #pragma unroll
        for (int i = 0; i < 2; i++) {
            int cid = tid + 256 * i;
            int r = cid >> 3, c = cid & 7;
            size_t gk = ((size_t)b * SS + kb * 64 + r) * H3 + HH + h * DHH + c * 8;
            size_t gv = gk + HH;
            uint32_t so = (uint32_t)(r * 128 + ((c ^ (r & 7)) << 4));
            cpa16(sk + so,         qkvh + gk);
            cpa16(sk + 8192 + so,  qkvl + gk);
            cpa16(sk + 16384 + so, qkvh + gv);
            cpa16(sk + 24576 + so, qkvl + gv);
        }
    };

    LOADKV(0, 0); CPA_COMMIT();

    float oacc[8][4];
    #pragma unroll
    for (int i = 0; i < 8; i++)
        #pragma unroll
        for (int j = 0; j < 4; j++) oacc[i][j] = 0.f;
    float m0 = -1e30f, m1 = -1e30f, l0 = 0.f, l1 = 0.f;

    for (int kb = 0; kb < 8; kb++) {
        bool more = (kb < 7);
        if (more) { LOADKV((kb + 1) & 1, kb + 1); CPA_COMMIT(); }
        if (more) cpa_wait1(); else cpa_wait0();
        __syncthreads();

        uint32_t stg = base + KV + (kb & 1) * 32768;
        float sacc[8][4];
        #pragma unroll
        for (int i = 0; i < 8; i++)
            #pragma unroll
            for (int j = 0; j < 4; j++) sacc[i][j] = 0.f;

        // ---- S = Q @ K^T  (128q x 64k) ----
        #pragma unroll
        for (int ks = 0; ks < 4; ks++) {
            uint32_t qhf[4], qlf[4];
            {
                int r = wid * 16 + (lane & 15);
                uint32_t so = (uint32_t)(r * 128 + (((ks * 2 + (lane >> 4)) ^ (r & 7)) << 4));
                ldm4(qhf, base + QH + so);
                ldm4(qlf, base + QL + so);
            }
            uint32_t khf[4][4], klf[4][4];
            #pragma unroll
            for (int g = 0; g < 4; g++) {
                int n = g * 16 + (lane & 15);
                uint32_t so = (uint32_t)(n * 128 + (((ks * 2 + (lane >> 4)) ^ (n & 7)) << 4));
                ldm4(khf[g], stg + so);
                ldm4(klf[g], stg + 8192 + so);
            }
            #pragma unroll
            for (int nf = 0; nf < 8; nf++) {
                int g = nf >> 1;
                uint32_t bh2[2] = { khf[g][nf & 1], khf[g][2 + (nf & 1)] };
                uint32_t bl2[2] = { klf[g][nf & 1], klf[g][2 + (nf & 1)] };
                mma16816(sacc[nf], qhf, bh2);
                mma16816(sacc[nf], qlf, bh2);
                mma16816(sacc[nf], qhf, bl2);
            }
        }

        // ---- online softmax ----
        float vmax0 = -1e30f, vmax1 = -1e30f;
        #pragma unroll
        for (int nf = 0; nf < 8; nf++) {
            int col = kb * 64 + nf * 8 + (lane & 3) * 2;
            float b0 = *(const float*)(bp + AMS + col * 4);
            float b1 = *(const float*)(bp + AMS + (col + 1) * 4);
            sacc[nf][0] = sacc[nf][0] * 0.125f + b0;
            sacc[nf][1] = sacc[nf][1] * 0.125f + b1;
            sacc[nf][2] = sacc[nf][2] * 0.125f + b0;
            sacc[nf][3] = sacc[nf][3] * 0.125f + b1;
            vmax0 = fmaxf(vmax0, fmaxf(sacc[nf][0], sacc[nf][1]));
            vmax1 = fmaxf(vmax1, fmaxf(sacc[nf][2], sacc[nf][3]));
        }
        vmax0 = fmaxf(vmax0, __shfl_xor_sync(0xffffffffu, vmax0, 1));
        vmax0 = fmaxf(vmax0, __shfl_xor_sync(0xffffffffu, vmax0, 2));
        vmax1 = fmaxf(vmax1, __shfl_xor_sync(0xffffffffu, vmax1, 1));
        vmax1 = fmaxf(vmax1, __shfl_xor_sync(0xffffffffu, vmax1, 2));
        float mn0 = fmaxf(m0, vmax0), mn1 = fmaxf(m1, vmax1);
        float f0 = __expf(m0 - mn0), f1 = __expf(m1 - mn1);
        float rs0 = 0.f, rs1 = 0.f;
        #pragma unroll
        for (int nf = 0; nf < 8; nf++) {
            sacc[nf][0] = __expf(sacc[nf][0] - mn0);
            sacc[nf][1] = __expf(sacc[nf][1] - mn0);
            sacc[nf][2] = __expf(sacc[nf][2] - mn1);
            sacc[nf][3] = __expf(sacc[nf][3] - mn1);
            rs0 += sacc[nf][0] + sacc[nf][1];
            rs1 += sacc[nf][2] + sacc[nf][3];
        }
        rs0 += __shfl_xor_sync(0xffffffffu, rs0, 1);
        rs0 += __shfl_xor_sync(0xffffffffu, rs0, 2);
        rs1 += __shfl_xor_sync(0xffffffffu, rs1, 1);
        rs1 += __shfl_xor_sync(0xffffffffu, rs1, 2);
        l0 = l0 * f0 + rs0;
        l1 = l1 * f1 + rs1;
        m0 = mn0; m1 = mn1;
        #pragma unroll
        for (int onf = 0; onf < 8; onf++) {
            oacc[onf][0] *= f0; oacc[onf][1] *= f0;
            oacc[onf][2] *= f1; oacc[onf][3] *= f1;
        }

        // ---- O += P @ V ----
        #pragma unroll
        for (int kp = 0; kp < 4; kp++) {
            uint32_t pph[4], ppl[4];
            {
                int nf0 = 2 * kp, nf1 = 2 * kp + 1;
                __nv_bfloat16 h0, h1, h2, h3, u0, u1, u2, u3;
                split1(sacc[nf0][0], h0, u0); split1(sacc[nf0][1], h1, u1);
                split1(sacc[nf0][2], h2, u2); split1(sacc[nf0][3], h3, u3);
                pph[0] = packbf2(h0, h1); ppl[0] = packbf2(u0, u1);
                pph[1] = packbf2(h2, h3); ppl[1] = packbf2(u2, u3);
                split1(sacc[nf1][0], h0, u0); split1(sacc[nf1][1], h1, u1);
                split1(sacc[nf1][2], h2, u2); split1(sacc[nf1][3], h3, u3);
                pph[2] = packbf2(h0, h1); ppl[2] = packbf2(u0, u1);
                pph[3] = packbf2(h2, h3); ppl[3] = packbf2(u2, u3);
            }
            uint32_t vhf[4][4], vlf[4][4];
            #pragma unroll
            for (int g = 0; g < 4; g++) {
                int idx = lane & 7, sel = lane >> 3;
                int k = kp * 16 + (sel & 1) * 8 + idx;
                int c = 2 * g + (sel >> 1);
                uint32_t so = (uint32_t)(k * 128 + ((c ^ (k & 7)) << 4));
                ldm4t(vhf[g], stg + 16384 + so);
                ldm4t(vlf[g], stg + 24576 + so);
            }
            #pragma unroll
            for (int onf = 0; onf < 8; onf++) {
                int g = onf >> 1;
                uint32_t vh2[2] = { vhf[g][(onf & 1) * 2], vhf[g][(onf & 1) * 2 + 1] };
                uint32_t vl2[2] = { vlf[g][(onf & 1) * 2], vlf[g][(onf & 1) * 2 + 1] };
                mma16816(oacc[onf], pph, vh2);
                mma16816(oacc[onf], ppl, vh2);
                mma16816(oacc[onf], pph, vl2);
            }
        }
        __syncthreads();
    }

    float il0 = 1.f / l0, il1 = 1.f / l1;
    size_t tok = tokq + wid * 16 + (lane >> 2);
    #pragma unroll
    for (int onf = 0; onf < 8; onf++) {
        int c = h * DHH + onf * 8 + (lane & 3) * 2;
        float v0 = oacc[onf][0] * il0, v1 = oacc[onf][1] * il0;
        float v2 = oacc[onf][2] * il1, v3 = oacc[onf][3] * il1;
        __nv_bfloat16 h0, h1, h2, h3, u0, u1, u2, u3;
        split1(v0, h0, u0); split1(v1, h1, u1);
        split1(v2, h2, u2); split1(v3, h3, u3);
        *(uint32_t*)&ctxh[tok * HH + c]       = packbf2(h0, h1);
        *(uint32_t*)&ctxl[tok * HH + c]       = packbf2(u0, u1);
        *(uint32_t*)&ctxh[(tok + 8) * HH + c] = packbf2(h2, h3);
        *(uint32_t*)&ctxl[(tok + 8) * HH + c] = packbf2(u2, u3);
    }
}

// ---------------- weight split: fp32 -> bf16 hi/lo ----------------
__global__ __launch_bounds__(256) void wsplit(
    const float4* __restrict__ w, __nv_bfloat162* __restrict__ h,
    __nv_bfloat162* __restrict__ l, int n4)
{
    int i = blockIdx.x * 256 + threadIdx.x;
    if (i >= n4) return;
    float4 v = w[i];
    __nv_bfloat16 h0, h1, h2, h3, l0, l1, l2, l3;
    split1(v.x, h0, l0); split1(v.y, h1, l1);
    split1(v.z, h2, l2); split1(v.w, h3, l3);
    __nv_bfloat162 a; a.x = h0; a.y = h1;
    __nv_bfloat162 b; b.x = h2; b.y = h3;
    __nv_bfloat162 c; c.x = l0; c.y = l1;
    __nv_bfloat162 d; d.x = l2; d.y = l3;
    h[i * 2] = a; h[i * 2 + 1] = b;
    l[i * 2] = c; l[i * 2 + 1] = d;
}

// ---------------- embedding + LayerNorm (+ split), float4-vectorized ----------------
__global__ __launch_bounds__(256) void embed_ln_kernel(
    const int* __restrict__ ids, const float* __restrict__ tok,
    const float* __restrict__ pos, const float* __restrict__ gs,
    const float* __restrict__ gb, float* __restrict__ out,
    __nv_bfloat16* __restrict__ oh, __nv_bfloat16* __restrict__ ol)
{
    int t  = blockIdx.x;
    int sp = t & (SS - 1);
    int id = ids[t];
    int j  = threadIdx.x;           // 0..255; active j<192 (768/4)
    float4 v4 = make_float4(0.f, 0.f, 0.f, 0.f);
    if (j < HH / 4) {
        float4 a = *(const float4*)&tok[(size_t)id * HH + j * 4];
        float4 p = *(const float4*)&pos[(size_t)sp * HH + j * 4];
        v4 = make_float4(a.x + p.x, a.y + p.y, a.z + p.z, a.w + p.w);
    }
    float s = v4.x + v4.y + v4.z + v4.w;
    float mean = block_sum_256(s) * (1.f / HH);
    float sq = 0.f;
    if (j < HH / 4) {
        float d0 = v4.x - mean, d1 = v4.y - mean, d2 = v4.z - mean, d3 = v4.w - mean;
        sq = d0 * d0 + d1 * d1 + d2 * d2 + d3 * d3;
    }
    float var = block_sum_256(sq) * (1.f / HH);
    float inv = rsqrtf(var + 1e-12f);
    if (j < HH / 4) {
        float4 g4 = *(const float4*)&gs[j * 4];
        float4 b4 = *(const float4*)&gb[j * 4];
        float r0 = (v4.x - mean) * inv * g4.x + b4.x;
        float r1 = (v4.y - mean) * inv * g4.y + b4.y;
        float r2 = (v4.z - mean) * inv * g4.z + b4.z;
        float r3 = (v4.w - mean) * inv * g4.w + b4.w;
        *(float4*)&out[(size_t)t * HH + j * 4] = make_float4(r0, r1, r2, r3);
        __nv_bfloat16 h0, h1, h2, h3, l0, l1, l2, l3;
        split1(r0, h0, l0); split1(r1, h1, l1);
        split1(r2, h2, l2); split1(r3, h3, l3);
        *(uint32_t*)&oh[(size_t)t * HH + j * 4]     = packbf2(h0, h1);
        *(uint32_t*)&oh[(size_t)t * HH + j * 4 + 2] = packbf2(h2, h3);
        *(uint32_t*)&ol[(size_t)t * HH + j * 4]     = packbf2(l0, l1);
        *(uint32_t*)&ol[(size_t)t * HH + j * 4 + 2] = packbf2(l2, l3);
    }
}

// ---------------- LayerNorm of (tmp + tmp2) -> x + split, float4-vectorized ----------------
__global__ __launch_bounds__(256) void ln_split2_kernel(
    const float* __restrict__ t_in, const float* __restrict__ t_in2,
    float* __restrict__ x,
    const float* __restrict__ gs, const float* __restrict__ gb,
    __nv_bfloat16* __restrict__ oh, __nv_bfloat16* __restrict__ ol)
{
    int t = blockIdx.x;
    int j = threadIdx.x;
    float4 v4 = make_float4(0.f, 0.f, 0.f, 0.f);
    if (j < HH / 4) {
        float4 a = *(const float4*)&t_in[(size_t)t * HH + j * 4];
        float4 b = *(const float4*)&t_in2[(size_t)t * HH + j * 4];
        v4 = make_float4(a.x + b.x, a.y + b.y, a.z + b.z, a.w + b.w);
    }
    float s = v4.x + v4.y + v4.z + v4.w;
    float mean = block_sum_256(s) * (1.f / HH);
    float sq = 0.f;
    if (j < HH / 4) {
        float d0 = v4.x - mean, d1 = v4.y - mean, d2 = v4.z - mean, d3 = v4.w - mean;
        sq = d0 * d0 + d1 * d1 + d2 * d2 + d3 * d3;
    }
    float var = block_sum_256(sq) * (1.f / HH);
    float inv = rsqrtf(var + 1e-12f);
    if (j < HH / 4) {
        float4 g4 = *(const float4*)&gs[j * 4];
        float4 b4 = *(const float4*)&gb[j * 4];
        float r0 = (v4.x - mean) * inv * g4.x + b4.x;
        float r1 = (v4.y - mean) * inv * g4.y + b4.y;
        float r2 = (v4.z - mean) * inv * g4.z + b4.z;
        float r3 = (v4.w - mean) * inv * g4.w + b4.w;
        *(float4*)&x[(size_t)t * HH + j * 4] = make_float4(r0, r1, r2, r3);
        __nv_bfloat16 h0, h1, h2, h3, l0, l1, l2, l3;
        split1(r0, h0, l0); split1(r1, h1, l1);
        split1(r2, h2, l2); split1(r3, h3, l3);
        *(uint32_t*)&oh[(size_t)t * HH + j * 4]     = packbf2(h0, h1);
        *(uint32_t*)&oh[(size_t)t * HH + j * 4 + 2] = packbf2(h2, h3);
        *(uint32_t*)&ol[(size_t)t * HH + j * 4]     = packbf2(l0, l1);
        *(uint32_t*)&ol[(size_t)t * HH + j * 4 + 2] = packbf2(l2, l3);
    }
}

// ---------------- small SIMT GEMM (classifier, N=9) ----------------
__global__ __launch_bounds__(256) void cls_gemm_kernel(
    const float* __restrict__ A, const float* __restrict__ B,
    const float* __restrict__ bias, float* __restrict__ C)
{
    int row = blockIdx.x * 8 + (threadIdx.x >> 5);
    int lane = threadIdx.x & 31;
    if (row >= TOK) return;
    const float* a = A + (size_t)row * HH;
    float acc[KK];
    #pragma unroll
    for (int j = 0; j < KK; j++) acc[j] = 0.f;
    for (int k = lane; k < HH; k += 32) {
        float av = a[k];
        const float* bp = B + (size_t)k * KK;
        #pragma unroll
        for (int j = 0; j < KK; j++) acc[j] += av * bp[j];
    }
    #pragma unroll
    for (int j = 0; j < KK; j++) {
        float s = warp_sum(acc[j]);
        if (lane == 0) C[(size_t)row * KK + j] = s + bias[j];
    }
}

// ---------------- CRF NLL (single block) ----------------
__global__ __launch_bounds__(256) void crf_kernel(
    const float* __restrict__ emis, const int* __restrict__ labels,
    const int* __restrict__ am, const float* __restrict__ cs,
    const float* __restrict__ ce, const float* __restrict__ ct,
    float* __restrict__ loss_out)
{
    __shared__ float alpha[BB][KK];
    __shared__ float trans[KK][KK];
    __shared__ float den[BB];
    __shared__ float num[BB];

    int tid = threadIdx.x;
    if (tid < KK * KK) trans[tid / KK][tid % KK] = ct[tid];
    __syncthreads();

    int b = tid / KK, j = tid - b * KK;
    bool act = tid < BB * KK;
    if (act) alpha[b][j] = cs[j] + emis[(size_t)(b * SS) * KK + j];
    __syncthreads();

    for (int s = 1; s < SS; s++) {
        float nv = 0.f;
        if (act) {
            int idx = b * SS + s;
            bool m = (labels[idx] != -100) && (am[idx] == 1);
            if (m) {
                float mx = -1e30f;
                #pragma unroll
                for (int i = 0; i < KK; i++) mx = fmaxf(mx, alpha[b][i] + trans[i][j]);
                float sum = 0.f;
                #pragma unroll
                for (int i = 0; i < KK; i++) sum += expf(alpha[b][i] + trans[i][j] - mx);
                nv = mx + logf(sum) + emis[(size_t)idx * KK + j];
            } else {
                nv = alpha[b][j];
            }
        }
        __syncthreads();
        if (act) alpha[b][j] = nv;
        __syncthreads();
    }

    if (act && j == 0) {
        float mx = -1e30f;
        #pragma unroll
        for (int i = 0; i < KK; i++) mx = fmaxf(mx, alpha[b][i] + ce[i]);
        float sum = 0.f;
        #pragma unroll
        for (int i = 0; i < KK; i++) sum += expf(alpha[b][i] + ce[i] - mx);
        den[b] = mx + logf(sum);
    }

    if (tid < BB) {
        int bb = tid;
        int l0 = labels[bb * SS];
        int t0 = (l0 == -100) ? 0 : l0;
        float sc = cs[t0] + emis[(size_t)(bb * SS) * KK + t0];
        int prev = t0;
        int cnt = 1;
        for (int s = 1; s < SS; s++) {
            int idx = bb * SS + s;
            int l = labels[idx];
            bool m = (l != -100) && (am[idx] == 1);
            int tg = (l == -100) ? 0 : l;
            if (m) {
                sc += trans[prev][tg] + emis[(size_t)idx * KK + tg];
                cnt++;
            }
            prev = tg;
        }
        int li = cnt - 1;
        int ll = labels[bb * SS + li];
        int lt = (ll == -100) ? 0 : ll;
        sc += ce[lt];
        num[bb] = sc;
    }
    __syncthreads();
    if (tid == 0) {
        float L = 0.f;
        for (int i = 0; i < BB; i++) L += num[i] - den[i];
        loss_out[0] = -(L / (float)BB);
    }
}

// ---------------- launch ----------------
extern "C" void kernel_launch(void* const* d_in, const int* in_sizes, int n_in,
                              void* d_out, int out_size)
{
    const int*   ids  = (const int*)d_in[0];
    const int*   am   = (const int*)d_in[1];
    const int*   lab  = (const int*)d_in[2];
    const float* etok = (const float*)d_in[3];
    const float* epos = (const float*)d_in[4];
    const float* elns = (const float*)d_in[5];
    const float* elnb = (const float*)d_in[6];
    const float* Wqkv = (const float*)d_in[7];
    const float* bqkv = (const float*)d_in[8];
    const float* Wo   = (const float*)d_in[9];
    const float* bo   = (const float*)d_in[10];
    const float* l1s  = (const float*)d_in[11];
    const float* l1b  = (const float*)d_in[12];
    const float* W1   = (const float*)d_in[13];
    const float* b1   = (const float*)d_in[14];
    const float* W2   = (const float*)d_in[15];
    const float* b2   = (const float*)d_in[16];
    const float* l2s  = (const float*)d_in[17];
    const float* l2b  = (const float*)d_in[18];
    const float* clsW = (const float*)d_in[19];
    const float* clsb = (const float*)d_in[20];
    const float* c_s  = (const float*)d_in[21];
    const float* c_e  = (const float*)d_in[22];
    const float* c_t  = (const float*)d_in[23];

    float *x, *tmp, *tmp2, *emis_s, *loss_s;
    __nv_bfloat16 *xh, *xl, *qkvh, *qkvl, *ffh, *ffl, *ctxh, *ctxl;
    __nv_bfloat16 *wqkvh, *wqkvl, *woh, *wol, *w1h, *w1l, *w2h, *w2l;
    cudaGetSymbolAddress((void**)&x,      g_x);
    cudaGetSymbolAddress((void**)&tmp,    g_tmp);
    cudaGetSymbolAddress((void**)&tmp2,   g_tmp2);
    cudaGetSymbolAddress((void**)&emis_s, g_emis);
    cudaGetSymbolAddress((void**)&loss_s, g_loss);
    cudaGetSymbolAddress((void**)&xh,     g_xh);
    cudaGetSymbolAddress((void**)&xl,     g_xl);
    cudaGetSymbolAddress((void**)&qkvh,   g_qkvh);
    cudaGetSymbolAddress((void**)&qkvl,   g_qkvl);
    cudaGetSymbolAddress((void**)&ffh,    g_ffh);
    cudaGetSymbolAddress((void**)&ffl,    g_ffl);
    cudaGetSymbolAddress((void**)&ctxh,   g_ctxh);
    cudaGetSymbolAddress((void**)&ctxl,   g_ctxl);
    cudaGetSymbolAddress((void**)&wqkvh,  g_wqkvh);
    cudaGetSymbolAddress((void**)&wqkvl,  g_wqkvl);
    cudaGetSymbolAddress((void**)&woh,    g_woh);
    cudaGetSymbolAddress((void**)&wol,    g_wol);
    cudaGetSymbolAddress((void**)&w1h,    g_w1h);
    cudaGetSymbolAddress((void**)&w1l,    g_w1l);
    cudaGetSymbolAddress((void**)&w2h,    g_w2h);
    cudaGetSymbolAddress((void**)&w2l,    g_w2l);

    const int EMIS = TOK * KK;
    float* out = (float*)d_out;
    float* emis_dst;
    float* loss_dst;
    if (out_size == EMIS + 1)      { loss_dst = out; emis_dst = out + 1; }
    else if (out_size == EMIS)     { loss_dst = loss_s; emis_dst = out; }
    else                           { loss_dst = out; emis_dst = emis_s; }

    const int SMG  = 3 * 32768 + 1024;       // g2: 97 KB -> 2 CTAs/SM
    const int SMFA = 1024 + 98304 + 2048;    // flash: ~100 KB -> 2 CTAs/SM
    cudaFuncSetAttribute(g2<0>,  cudaFuncAttributeMaxDynamicSharedMemorySize, SMG);
    cudaFuncSetAttribute(g2<2>,  cudaFuncAttributeMaxDynamicSharedMemorySize, SMG);
    cudaFuncSetAttribute(g2<3>,  cudaFuncAttributeMaxDynamicSharedMemorySize, SMG);
    cudaFuncSetAttribute(g2<12>, cudaFuncAttributeMaxDynamicSharedMemorySize, SMG);
    cudaFuncSetAttribute(flash_kernel, cudaFuncAttributeMaxDynamicSharedMemorySize, SMFA);

    // ---- one-time (per launch) weight splits ----
    {
        int n4;
        n4 = LL * HH * H3 / 4;
        wsplit<<<(n4 + 255) / 256, 256>>>((const float4*)Wqkv, (__nv_bfloat162*)wqkvh, (__nv_bfloat162*)wqkvl, n4);
        n4 = LL * HH * HH / 4;
        wsplit<<<(n4 + 255) / 256, 256>>>((const float4*)Wo,   (__nv_bfloat162*)woh,   (__nv_bfloat162*)wol,   n4);
        n4 = LL * HH * FFD / 4;
        wsplit<<<(n4 + 255) / 256, 256>>>((const float4*)W1,   (__nv_bfloat162*)w1h,   (__nv_bfloat162*)w1l,   n4);
        n4 = LL * FFD * HH / 4;
        wsplit<<<(n4 + 255) / 256, 256>>>((const float4*)W2,   (__nv_bfloat162*)w2h,   (__nv_bfloat162*)w2l,   n4);
    }

    embed_ln_kernel<<<TOK, 256>>>(ids, etok, epos, elns, elnb, x, xh, xl);

    for (int l = 0; l < LL; l++) {
        const float* bqkv_l = bqkv + (size_t)l * H3;
        const float* bo_l   = bo   + (size_t)l * HH;
        const float* l1s_l  = l1s  + (size_t)l * HH;
        const float* l1b_l  = l1b  + (size_t)l * HH;
        const float* b1_l   = b1   + (size_t)l * FFD;
        const float* b2_l   = b2   + (size_t)l * HH;
        const float* l2s_l  = l2s  + (size_t)l * HH;
        const float* l2b_l  = l2b  + (size_t)l * HH;
        const __nv_bfloat16* wqkvh_l = wqkvh + (size_t)l * HH * H3;
        const __nv_bfloat16* wqkvl_l = wqkvl + (size_t)l * HH * H3;
        const __nv_bfloat16* woh_l   = woh   + (size_t)l * HH * HH;
        const __nv_bfloat16* wol_l   = wol   + (size_t)l * HH * HH;
        const __nv_bfloat16* w1h_l   = w1h   + (size_t)l * HH * FFD;
        const __nv_bfloat16* w1l_l   = w1l   + (size_t)l * HH * FFD;
        const __nv_bfloat16* w2h_l   = w2h   + (size_t)l * FFD * HH;
        const __nv_bfloat16* w2l_l   = w2l   + (size_t)l * FFD * HH;

        // qkv = x @ Wqkv + bqkv  -> split   [8192,2304], K=768
        g2<2><<<dim3(H3 / 128, TOK / 128), 256, SMG>>>(
            HH, xh, xl, HH, wqkvh_l, wqkvl_l, H3,
            nullptr, qkvh, qkvl, H3, bqkv_l, nullptr, nullptr);

        // fused attention -> ctx hi/lo
        flash_kernel<<<dim3(SS / 128, BB * NHH), 256, SMFA>>>(qkvh, qkvl, am, ctxh, ctxl);

        // tmp(+tmp2) = x + ctx @ Wo + bo   split-K=2, [8192,768], K=2x384
        g2<12><<<dim3(HH / 128, TOK / 128, 2), 256, SMG>>>(
            HH / 2, ctxh, ctxl, HH, woh_l, wol_l, HH,
            tmp, nullptr, nullptr, HH, bo_l, x, tmp2);
        ln_split2_kernel<<<TOK, 256>>>(tmp, tmp2, x, l1s_l, l1b_l, xh, xl);

        // ff = gelu(x @ W1 + b1)  -> split   [8192,3072], K=768
        g2<3><<<dim3(FFD / 128, TOK / 128), 256, SMG>>>(
            HH, xh, xl, HH, w1h_l, w1l_l, FFD,
            nullptr, ffh, ffl, FFD, b1_l, nullptr, nullptr);

        // tmp(+tmp2) = x + ff @ W2 + b2   split-K=2, [8192,768], K=2x1536
        g2<12><<<dim3(HH / 128, TOK / 128, 2), 256, SMG>>>(
            FFD / 2, ffh, ffl, FFD, w2h_l, w2l_l, HH,
            tmp, nullptr, nullptr, HH, b2_l, x, tmp2);
        ln_split2_kernel<<<TOK, 256>>>(tmp, tmp2, x, l2s_l, l2b_l, xh, xl);
    }

    // emissions = x @ cls_W + cls_b   [8192, 9]
    cls_gemm_kernel<<<TOK / 8, 256>>>(x, clsW, clsb, emis_dst);

    // CRF loss
    crf_kernel<<<1, 256>>>(emis_dst, lab, am, c_s, c_e, c_t, loss_dst);
}